// round 14
// baseline (speedup 1.0000x reference)
#include <cuda_runtime.h>
#include <stdint.h>

// Key space: b<256 (8 bits), px,py,pz<128 (7 bits each) -> 29-bit keys.
#define NKEYS    (1u << 29)
#define NWORDS   (1u << 24)         // NKEYS / 32
#define NG4      (NWORDS / 4)       // prefix granularity: 4 words = 16B
#define WPT      8                  // words per thread in emit
#define CTA      256
#define WPB      (WPT * CTA)        // 2048 words per block
#define NCHUNK   (NWORDS / WPB)     // 8192 emit blocks
#define NMAX     4000000
#define EMIT_CAP 1024               // smem key capacity per block (mean ~488)

__device__ __align__(16) unsigned int g_bitmap[NWORDS];   // 64 MB, zero at load
__device__ __align__(16) unsigned int g_prefix4[NG4];     // 16 MB
__device__ __align__(16) unsigned int g_kp[NMAX];         // 16 MB: key<<3 | pos
__device__ unsigned int g_state[NCHUNK];                  // lookback: val<<2|flag
__device__ unsigned int g_total;

static __device__ __forceinline__ unsigned make_key(int4 c) {
    unsigned b  = (unsigned)c.x;
    unsigned px = (unsigned)c.y >> 1;
    unsigned py = (unsigned)c.z >> 1;
    unsigned pz = (unsigned)c.w >> 1;
    return (((b << 7 | px) << 7 | py) << 7) | pz;
}

__global__ void k_nop() {}

// ---- K1: scatter presence bits (RED.OR) + stash key/pos, 4 pts/thread -----
static __device__ __forceinline__ void scatter_one(int4 c, int i) {
    unsigned key = make_key(c);
    unsigned pos = ((unsigned)c.y & 1u) | (((unsigned)c.z & 1u) << 1) | (((unsigned)c.w & 1u) << 2);
    __stwt(&g_kp[i], (key << 3) | pos);
    atomicOr(&g_bitmap[key >> 5], 1u << (key & 31));   // result unused -> RED.OR
}

__global__ void k_scatter(const int4* __restrict__ coords, int n) {
    int T = gridDim.x * blockDim.x;
    int i0 = blockIdx.x * blockDim.x + threadIdx.x;
    int4 c0, c1, c2, c3;
    int i1 = i0 + T, i2 = i0 + 2 * T, i3 = i0 + 3 * T;
    bool v0 = i0 < n, v1 = i1 < n, v2 = i2 < n, v3 = i3 < n;
    if (v0) c0 = coords[i0];
    if (v1) c1 = coords[i1];
    if (v2) c2 = coords[i2];
    if (v3) c3 = coords[i3];
    if (v0) scatter_one(c0, i0);
    if (v1) scatter_one(c1, i1);
    if (v2) scatter_one(c2, i2);
    if (v3) scatter_one(c3, i3);
}

// ---- K2: emit with fused decoupled-lookback scan --------------------------
__global__ void __launch_bounds__(CTA)
k_emit(float4* __restrict__ out_coords, float* __restrict__ out_feats) {
    __shared__ unsigned wexc[32];
    __shared__ unsigned s_keys[EMIT_CAP];
    __shared__ unsigned s_base, s_agg;
    int t = threadIdx.x;
    int bid = blockIdx.x;
    unsigned base = bid * WPB + t * WPT;
    unsigned words[WPT];
    const uint4* p = reinterpret_cast<const uint4*>(&g_bitmap[base]);
#pragma unroll
    for (int j = 0; j < WPT / 4; j++) {
        uint4 v = p[j];
        words[j * 4 + 0] = v.x; words[j * 4 + 1] = v.y;
        words[j * 4 + 2] = v.z; words[j * 4 + 3] = v.w;
    }
    unsigned tsum = 0;
#pragma unroll
    for (int j = 0; j < WPT; j++) tsum += __popc(words[j]);

    // block exclusive scan of per-thread sums
    int lane = t & 31, warp = t >> 5;
    unsigned x = tsum;
    for (int o = 1; o < 32; o <<= 1) {
        unsigned y = __shfl_up_sync(0xffffffffu, x, o);
        if (lane >= o) x += y;
    }
    if (lane == 31) wexc[warp] = x;
    __syncthreads();
    if (warp == 0) {   // all 32 lanes participate (shfl safety)
        unsigned y = (lane < CTA / 32) ? wexc[lane] : 0u;
        unsigned orig = y;
        for (int o = 1; o < 32; o <<= 1) {
            unsigned z = __shfl_up_sync(0xffffffffu, y, o);
            if (lane >= o) y += z;
        }
        if (lane < CTA / 32) wexc[lane] = y - orig;
    }
    __syncthreads();
    if (t == CTA - 1) s_agg = wexc[warp] + x;   // block aggregate
    __syncthreads();
    unsigned lexc = wexc[warp] + (x - tsum);    // block-local exclusive rank
    unsigned aggv = s_agg;

    // ---- decoupled lookback (warp 0) ----
    if (warp == 0) {
        volatile unsigned* st = g_state;
        if (bid == 0) {
            if (lane == 0) {
                st[0] = (aggv << 2) | 2u;
                s_base = 0u;
            }
        } else {
            if (lane == 0) st[bid] = (aggv << 2) | 1u;   // publish aggregate
            unsigned running = 0;
            int lb = bid - 1;
            while (true) {
                int idx = lb - lane;           // lane 0 = closest predecessor
                unsigned s;
                if (idx >= 0) {
                    do { s = st[idx]; } while ((s & 3u) == 0u);
                } else {
                    s = 2u;                    // virtual inclusive-0 before block 0
                }
                unsigned mask = __ballot_sync(0xffffffffu, (s & 3u) == 2u);
                int firstP = __ffs(mask) - 1;  // closest inclusive publisher
                unsigned val = s >> 2;
                unsigned contrib = mask ? ((lane <= (unsigned)firstP) ? val : 0u) : val;
                for (int o = 16; o > 0; o >>= 1)
                    contrib += __shfl_down_sync(0xffffffffu, contrib, o);
                contrib = __shfl_sync(0xffffffffu, contrib, 0);
                running += contrib;
                if (mask) break;
                lb -= 32;
            }
            if (lane == 0) {
                st[bid] = ((running + aggv) << 2) | 2u;   // publish inclusive
                s_base = running;
                if (bid == NCHUNK - 1) g_total = running + aggv;
            }
        }
    }
    __syncthreads();

    unsigned gbase = s_base;
    unsigned lrun = lexc;

    // prefix at 4-word granularity: 2 entries per thread (WPT==8)
    unsigned c03 = __popc(words[0]) + __popc(words[1]) + __popc(words[2]) + __popc(words[3]);
    g_prefix4[(base >> 2) + 0] = gbase + lrun;
    g_prefix4[(base >> 2) + 1] = gbase + lrun + c03;

    // phase 1: decode set bits (64-bit pairs) into smem at local rank
#pragma unroll
    for (int j2 = 0; j2 < WPT / 2; j2++) {
        unsigned long long m = (unsigned long long)words[2 * j2] |
                               ((unsigned long long)words[2 * j2 + 1] << 32);
        unsigned kbase = (base + 2 * j2) << 5;
        while (m) {
            unsigned b = (unsigned)__ffsll((long long)m) - 1u;
            m &= m - 1ull;
            unsigned key = kbase + b;
            if (lrun < EMIT_CAP) {
                s_keys[lrun] = key;
            } else {            // overflow spill (statistically never taken)
                __stwt(&out_coords[gbase + lrun], make_float4(
                    (float)(key >> 21), (float)((key >> 14) & 127u),
                    (float)((key >> 7) & 127u), (float)(key & 127u)));
                __stwt(&out_feats[gbase + lrun], 0.0f);
            }
            lrun++;
        }
    }
    __syncthreads();

    // phase 2: coalesced write of coords + zero feats
    unsigned tot = aggv < EMIT_CAP ? aggv : EMIT_CAP;
    for (unsigned i = t; i < tot; i += CTA) {
        unsigned key = s_keys[i];
        __stwt(&out_coords[gbase + i], make_float4(
            (float)(key >> 21), (float)((key >> 14) & 127u),
            (float)((key >> 7) & 127u), (float)(key & 127u)));
        __stwt(&out_feats[gbase + i], 0.0f);
    }
}

// ---- K3: per-input rank lookup + atomicAdd feats, 2 points/thread ---------
__global__ void k_feats(const float* __restrict__ kern,
                        float* __restrict__ out_feats, int n) {
    int T = gridDim.x * blockDim.x;
    int i0 = blockIdx.x * blockDim.x + threadIdx.x;
    int i1 = i0 + T;
    bool v1 = i1 < n;
    if (i0 >= n) return;

    unsigned kp0 = __ldcs(&g_kp[i0]);
    unsigned kp1 = v1 ? __ldcs(&g_kp[i1]) : 0u;

    unsigned key0 = kp0 >> 3, pos0 = kp0 & 7u;
    unsigned key1 = kp1 >> 3, pos1 = kp1 & 7u;
    unsigned w0 = key0 >> 5, g0 = w0 >> 2;
    unsigned w1 = key1 >> 5, g1 = w1 >> 2;

    // front-batch gathers: one 16B bitmap quad + one prefix word per point
    const uint4* bm = reinterpret_cast<const uint4*>(g_bitmap);
    uint4 a = __ldg(&bm[g0]);
    uint4 b = v1 ? __ldg(&bm[g1]) : make_uint4(0, 0, 0, 0);
    unsigned r0 = __ldg(&g_prefix4[g0]);
    unsigned r1 = v1 ? __ldg(&g_prefix4[g1]) : 0u;

    {
        unsigned sub = w0 & 3u, bit = key0 & 31u;
        unsigned ws[4] = {a.x, a.y, a.z, a.w};
#pragma unroll
        for (unsigned j = 0; j < 4; j++)
            if (j < sub) r0 += __popc(ws[j]);
        r0 += __popc(ws[sub] & ((1u << bit) - 1u));
        atomicAdd(&out_feats[r0], (float)(1u << pos0) * __ldg(&kern[pos0]));
    }
    if (v1) {
        unsigned sub = w1 & 3u, bit = key1 & 31u;
        unsigned ws[4] = {b.x, b.y, b.z, b.w};
#pragma unroll
        for (unsigned j = 0; j < 4; j++)
            if (j < sub) r1 += __popc(ws[j]);
        r1 += __popc(ws[sub] & ((1u << bit) - 1u));
        atomicAdd(&out_feats[r1], (float)(1u << pos1) * __ldg(&kern[pos1]));
    }
}

// ---- K4: merged tail-fill + bitmap/state reset ----------------------------
__global__ void k_finish(float4* __restrict__ out_coords, float* __restrict__ out_feats, int n) {
    unsigned gid = blockIdx.x * blockDim.x + threadIdx.x;
    unsigned stride = gridDim.x * blockDim.x;
    float4 neg = make_float4(-1.f, -1.f, -1.f, -1.f);
    unsigned total = g_total;
    for (unsigned i = total + gid; i < (unsigned)n; i += stride) {
        __stwt(&out_coords[i], neg);
        __stwt(&out_feats[i], 0.0f);
    }
    uint4 z = make_uint4(0u, 0u, 0u, 0u);
    uint4* p = reinterpret_cast<uint4*>(g_bitmap);
    unsigned n4 = NWORDS / 4;
    for (unsigned i = gid; i < n4; i += stride)
        p[i] = z;
    if (gid < NCHUNK) g_state[gid] = 0u;
}

extern "C" void kernel_launch(void* const* d_in, const int* in_sizes, int n_in,
                              void* d_out, int out_size) {
    const int4*  coords = (const int4*)d_in[0];
    const float* kern   = (const float*)d_in[1];
    int n = in_sizes[0] / 4;                // 4,000,000

    float*  out   = (float*)d_out;
    float4* out_c = (float4*)out;           // [n,4] coords as floats
    float*  out_f = out + (size_t)4 * n;    // [n] feats

    int gin2 = (n / 2 + 255) / 256;         // 2 points per thread (feats)
    int gin4 = (n / 4 + 255) / 256;         // 4 points per thread (scatter)

    k_nop    <<<1, 32>>>();                 // slot padding: emit -> slot 4
    k_nop    <<<1, 32>>>();
    k_scatter<<<gin4, 256>>>(coords, n);
    k_emit   <<<NCHUNK, CTA>>>(out_c, out_f);   // profiled this round
    k_feats  <<<gin2, 256>>>(kern, out_f, n);
    k_finish <<<2048, 256>>>(out_c, out_f, n);
}

// round 15
// speedup vs baseline: 1.0112x; 1.0112x over previous
#include <cuda_runtime.h>
#include <stdint.h>

// Key space: b<256 (8 bits), px,py,pz<128 (7 bits each) -> 29-bit keys.
#define NKEYS    (1u << 29)
#define NWORDS   (1u << 24)         // NKEYS / 32
#define NG4      (NWORDS / 4)       // prefix granularity: 4 words = 16B
#define WPT      8                  // words per thread in emit/reduce
#define CTA      256
#define WPB      (WPT * CTA)        // 2048 words per block
#define NCHUNK   (NWORDS / WPB)     // 8192 chunks
#define NMAX     4000000
#define EMIT_CAP 1024               // smem key capacity per block (mean ~488)

__device__ __align__(16) unsigned int g_bitmap[NWORDS];   // 64 MB, zero at load
__device__ __align__(16) unsigned int g_prefix4[NG4];     // 16 MB
__device__ __align__(16) unsigned int g_kp[NMAX];         // 16 MB: key<<3 | pos
__device__ unsigned int g_chunk[NCHUNK];                  // counts -> offsets
__device__ unsigned int g_total;

static __device__ __forceinline__ unsigned make_key(int4 c) {
    unsigned b  = (unsigned)c.x;
    unsigned px = (unsigned)c.y >> 1;
    unsigned py = (unsigned)c.z >> 1;
    unsigned pz = (unsigned)c.w >> 1;
    return (((b << 7 | px) << 7 | py) << 7) | pz;
}

// ---- K1: scatter presence bits (RED.OR, no return) + stash key/pos --------
static __device__ __forceinline__ void scatter_one(int4 c, int i) {
    unsigned key = make_key(c);
    unsigned pos = ((unsigned)c.y & 1u) | (((unsigned)c.z & 1u) << 1) | (((unsigned)c.w & 1u) << 2);
    __stwt(&g_kp[i], (key << 3) | pos);
    atomicOr(&g_bitmap[key >> 5], 1u << (key & 31));   // result unused -> RED.OR
}

__global__ void k_scatter(const int4* __restrict__ coords, int n) {
    int T = gridDim.x * blockDim.x;
    int i0 = blockIdx.x * blockDim.x + threadIdx.x;
    int4 c0, c1, c2, c3;
    int i1 = i0 + T, i2 = i0 + 2 * T, i3 = i0 + 3 * T;
    bool v0 = i0 < n, v1 = i1 < n, v2 = i2 < n, v3 = i3 < n;
    if (v0) c0 = coords[i0];
    if (v1) c1 = coords[i1];
    if (v2) c2 = coords[i2];
    if (v3) c3 = coords[i3];
    if (v0) scatter_one(c0, i0);
    if (v1) scatter_one(c1, i1);
    if (v2) scatter_one(c2, i2);
    if (v3) scatter_one(c3, i3);
}

// ---- K2: per-chunk popcount sums (streaming 64MB read) --------------------
__global__ void __launch_bounds__(CTA) k_reduce() {
    __shared__ unsigned wsum[CTA / 32];
    unsigned base = blockIdx.x * WPB + threadIdx.x * WPT;
    const uint4* p = reinterpret_cast<const uint4*>(&g_bitmap[base]);
    uint4 v0 = p[0], v1 = p[1];
    unsigned s = __popc(v0.x) + __popc(v0.y) + __popc(v0.z) + __popc(v0.w)
               + __popc(v1.x) + __popc(v1.y) + __popc(v1.z) + __popc(v1.w);
    for (int o = 16; o > 0; o >>= 1) s += __shfl_down_sync(0xffffffffu, s, o);
    int lane = threadIdx.x & 31, warp = threadIdx.x >> 5;
    if (lane == 0) wsum[warp] = s;
    __syncthreads();
    if (threadIdx.x == 0) {
        unsigned t = 0;
#pragma unroll
        for (int w = 0; w < CTA / 32; w++) t += wsum[w];
        g_chunk[blockIdx.x] = t;
    }
}

// ---- K3: exclusive scan of 8192 chunk counts (single block) ---------------
__global__ void k_scan() {
    __shared__ unsigned sh[1024];
    int t = threadIdx.x;
    unsigned v[8], s = 0;
#pragma unroll
    for (int j = 0; j < 8; j++) { v[j] = g_chunk[t * 8 + j]; s += v[j]; }
    sh[t] = s;
    __syncthreads();
    for (int off = 1; off < 1024; off <<= 1) {
        unsigned x = (t >= off) ? sh[t - off] : 0u;
        __syncthreads();
        sh[t] += x;
        __syncthreads();
    }
    unsigned run = sh[t] - s;
#pragma unroll
    for (int j = 0; j < 8; j++) { g_chunk[t * 8 + j] = run; run += v[j]; }
    if (t == 1023) g_total = run;
}

// ---- K4: emit — phase1 decode keys->smem, phase2 coalesced coord+feat out -
__global__ void __launch_bounds__(CTA)
k_emit(float4* __restrict__ out_coords, float* __restrict__ out_feats) {
    __shared__ unsigned wexc[32];
    __shared__ unsigned s_keys[EMIT_CAP];
    __shared__ unsigned s_base, s_agg;
    int t = threadIdx.x;
    unsigned base = blockIdx.x * WPB + t * WPT;
    unsigned words[WPT];
    const uint4* p = reinterpret_cast<const uint4*>(&g_bitmap[base]);
#pragma unroll
    for (int j = 0; j < WPT / 4; j++) {
        uint4 v = p[j];
        words[j * 4 + 0] = v.x; words[j * 4 + 1] = v.y;
        words[j * 4 + 2] = v.z; words[j * 4 + 3] = v.w;
    }
    unsigned tsum = 0;
#pragma unroll
    for (int j = 0; j < WPT; j++) tsum += __popc(words[j]);

    // block exclusive scan of per-thread sums
    int lane = t & 31, warp = t >> 5;
    unsigned x = tsum;
    for (int o = 1; o < 32; o <<= 1) {
        unsigned y = __shfl_up_sync(0xffffffffu, x, o);
        if (lane >= o) x += y;
    }
    if (lane == 31) wexc[warp] = x;
    __syncthreads();
    if (warp == 0) {   // all 32 lanes participate (shfl safety)
        unsigned y = (lane < CTA / 32) ? wexc[lane] : 0u;
        unsigned orig = y;
        for (int o = 1; o < 32; o <<= 1) {
            unsigned z = __shfl_up_sync(0xffffffffu, y, o);
            if (lane >= o) y += z;
        }
        if (lane < CTA / 32) wexc[lane] = y - orig;
    }
    __syncthreads();

    if (t == 0) s_base = g_chunk[blockIdx.x];
    if (t == CTA - 1) s_agg = wexc[warp] + x;   // block total unique
    __syncthreads();

    unsigned gbase = s_base;
    unsigned aggv = s_agg;
    unsigned lrun = wexc[warp] + (x - tsum);    // block-local rank

    // prefix at 4-word granularity: 2 entries per thread (WPT==8)
    unsigned c03 = __popc(words[0]) + __popc(words[1]) + __popc(words[2]) + __popc(words[3]);
    g_prefix4[(base >> 2) + 0] = gbase + lrun;
    g_prefix4[(base >> 2) + 1] = gbase + lrun + c03;

    // phase 1: decode set bits (64-bit pairs) into smem at local rank
#pragma unroll
    for (int j2 = 0; j2 < WPT / 2; j2++) {
        unsigned long long m = (unsigned long long)words[2 * j2] |
                               ((unsigned long long)words[2 * j2 + 1] << 32);
        unsigned kbase = (base + 2 * j2) << 5;
        while (m) {
            unsigned b = (unsigned)__ffsll((long long)m) - 1u;
            m &= m - 1ull;
            unsigned key = kbase + b;
            if (lrun < EMIT_CAP) {
                s_keys[lrun] = key;
            } else {            // overflow spill (statistically never taken)
                __stwt(&out_coords[gbase + lrun], make_float4(
                    (float)(key >> 21), (float)((key >> 14) & 127u),
                    (float)((key >> 7) & 127u), (float)(key & 127u)));
                __stwt(&out_feats[gbase + lrun], 0.0f);
            }
            lrun++;
        }
    }
    __syncthreads();

    // phase 2: coalesced write of coords + zero feats
    unsigned tot = aggv < EMIT_CAP ? aggv : EMIT_CAP;
    for (unsigned i = t; i < tot; i += CTA) {
        unsigned key = s_keys[i];
        __stwt(&out_coords[gbase + i], make_float4(
            (float)(key >> 21), (float)((key >> 14) & 127u),
            (float)((key >> 7) & 127u), (float)(key & 127u)));
        __stwt(&out_feats[gbase + i], 0.0f);
    }
}

// ---- K5: per-input rank lookup + atomicAdd feats, 2 points/thread ---------
__global__ void k_feats(const float* __restrict__ kern,
                        float* __restrict__ out_feats, int n) {
    int T = gridDim.x * blockDim.x;
    int i0 = blockIdx.x * blockDim.x + threadIdx.x;
    int i1 = i0 + T;
    bool v1 = i1 < n;
    if (i0 >= n) return;

    unsigned kp0 = __ldcs(&g_kp[i0]);
    unsigned kp1 = v1 ? __ldcs(&g_kp[i1]) : 0u;

    unsigned key0 = kp0 >> 3, pos0 = kp0 & 7u;
    unsigned key1 = kp1 >> 3, pos1 = kp1 & 7u;
    unsigned w0 = key0 >> 5, g0 = w0 >> 2;
    unsigned w1 = key1 >> 5, g1 = w1 >> 2;

    // front-batch gathers: one 16B bitmap quad + one prefix word per point
    const uint4* bm = reinterpret_cast<const uint4*>(g_bitmap);
    uint4 a = __ldg(&bm[g0]);
    uint4 b = v1 ? __ldg(&bm[g1]) : make_uint4(0, 0, 0, 0);
    unsigned r0 = __ldg(&g_prefix4[g0]);
    unsigned r1 = v1 ? __ldg(&g_prefix4[g1]) : 0u;

    {
        unsigned sub = w0 & 3u, bit = key0 & 31u;
        unsigned ws[4] = {a.x, a.y, a.z, a.w};
#pragma unroll
        for (unsigned j = 0; j < 4; j++)
            if (j < sub) r0 += __popc(ws[j]);
        r0 += __popc(ws[sub] & ((1u << bit) - 1u));
        atomicAdd(&out_feats[r0], (float)(1u << pos0) * __ldg(&kern[pos0]));
    }
    if (v1) {
        unsigned sub = w1 & 3u, bit = key1 & 31u;
        unsigned ws[4] = {b.x, b.y, b.z, b.w};
#pragma unroll
        for (unsigned j = 0; j < 4; j++)
            if (j < sub) r1 += __popc(ws[j]);
        r1 += __popc(ws[sub] & ((1u << bit) - 1u));
        atomicAdd(&out_feats[r1], (float)(1u << pos1) * __ldg(&kern[pos1]));
    }
}

// ---- K6: merged tail-fill + bitmap reset ----------------------------------
// (g_chunk is fully overwritten by k_reduce each call -> no reset needed)
__global__ void k_finish(float4* __restrict__ out_coords, float* __restrict__ out_feats, int n) {
    unsigned gid = blockIdx.x * blockDim.x + threadIdx.x;
    unsigned stride = gridDim.x * blockDim.x;
    float4 neg = make_float4(-1.f, -1.f, -1.f, -1.f);
    unsigned total = g_total;
    for (unsigned i = total + gid; i < (unsigned)n; i += stride) {
        __stwt(&out_coords[i], neg);
        __stwt(&out_feats[i], 0.0f);
    }
    uint4 z = make_uint4(0u, 0u, 0u, 0u);
    uint4* p = reinterpret_cast<uint4*>(g_bitmap);
    unsigned n4 = NWORDS / 4;
    for (unsigned i = gid; i < n4; i += stride)
        p[i] = z;
}

extern "C" void kernel_launch(void* const* d_in, const int* in_sizes, int n_in,
                              void* d_out, int out_size) {
    const int4*  coords = (const int4*)d_in[0];
    const float* kern   = (const float*)d_in[1];
    int n = in_sizes[0] / 4;                // 4,000,000

    float*  out   = (float*)d_out;
    float4* out_c = (float4*)out;           // [n,4] coords as floats
    float*  out_f = out + (size_t)4 * n;    // [n] feats

    int gin2 = (n / 2 + 255) / 256;         // 2 points per thread (feats)
    int gin4 = (n / 4 + 255) / 256;         // 4 points per thread (scatter)

    k_scatter<<<gin4, 256>>>(coords, n);
    k_reduce <<<NCHUNK, CTA>>>();
    k_scan   <<<1, 1024>>>();
    k_emit   <<<NCHUNK, CTA>>>(out_c, out_f);   // slot 4: profiled
    k_feats  <<<gin2, 256>>>(kern, out_f, n);
    k_finish <<<2048, 256>>>(out_c, out_f, n);
}

// round 16
// speedup vs baseline: 1.2815x; 1.2673x over previous
#include <cuda_runtime.h>
#include <stdint.h>

// Key space: b<256 (8 bits), px,py,pz<128 (7 bits each) -> 29-bit keys.
#define NKEYS    (1u << 29)
#define NWORDS   (1u << 24)         // NKEYS / 32
#define NG4      (NWORDS / 4)       // prefix granularity: 4 words = 16B
#define WPT      8                  // words per thread in emit/reduce
#define CTA      256
#define WPB      (WPT * CTA)        // 2048 words per block
#define NCHUNK   (NWORDS / WPB)     // 8192 chunks
#define NMAX     4000000
#define EMIT_CAP 1024               // smem key capacity per block (mean ~488)

__device__ __align__(16) unsigned int g_bitmap[NWORDS];   // 64 MB, zero at load
__device__ __align__(16) unsigned int g_prefix4[NG4];     // 16 MB
__device__ __align__(16) unsigned int g_kp[NMAX];         // 16 MB: key<<3 | pos
__device__ unsigned int g_chunk[NCHUNK];                  // counts -> offsets
__device__ unsigned int g_total;
__device__ unsigned int g_done;                           // reduce ticket (self-resetting)

static __device__ __forceinline__ unsigned make_key(int4 c) {
    unsigned b  = (unsigned)c.x;
    unsigned px = (unsigned)c.y >> 1;
    unsigned py = (unsigned)c.z >> 1;
    unsigned pz = (unsigned)c.w >> 1;
    return (((b << 7 | px) << 7 | py) << 7) | pz;
}

// ---- K1: scatter presence bits (RED.OR) + stash key/pos, 4 pts/thread -----
// coords read with __ldcs (streaming) so the bitmap stays L2-resident.
static __device__ __forceinline__ void scatter_one(int4 c, int i) {
    unsigned key = make_key(c);
    unsigned pos = ((unsigned)c.y & 1u) | (((unsigned)c.z & 1u) << 1) | (((unsigned)c.w & 1u) << 2);
    __stwt(&g_kp[i], (key << 3) | pos);
    atomicOr(&g_bitmap[key >> 5], 1u << (key & 31));   // result unused -> RED.OR
}

__global__ void k_scatter(const int4* __restrict__ coords, int n) {
    int T = gridDim.x * blockDim.x;
    int i0 = blockIdx.x * blockDim.x + threadIdx.x;
    int4 c0, c1, c2, c3;
    int i1 = i0 + T, i2 = i0 + 2 * T, i3 = i0 + 3 * T;
    bool v0 = i0 < n, v1 = i1 < n, v2 = i2 < n, v3 = i3 < n;
    if (v0) c0 = __ldcs(&coords[i0]);
    if (v1) c1 = __ldcs(&coords[i1]);
    if (v2) c2 = __ldcs(&coords[i2]);
    if (v3) c3 = __ldcs(&coords[i3]);
    if (v0) scatter_one(c0, i0);
    if (v1) scatter_one(c1, i1);
    if (v2) scatter_one(c2, i2);
    if (v3) scatter_one(c3, i3);
}

// ---- K2: per-chunk popcount sums + fused last-block exclusive scan --------
__global__ void __launch_bounds__(CTA) k_reduce() {
    __shared__ unsigned wsum[CTA / 32];
    __shared__ bool is_last;
    unsigned base = blockIdx.x * WPB + threadIdx.x * WPT;
    const uint4* p = reinterpret_cast<const uint4*>(&g_bitmap[base]);
    uint4 v0 = p[0], v1 = p[1];
    unsigned s = __popc(v0.x) + __popc(v0.y) + __popc(v0.z) + __popc(v0.w)
               + __popc(v1.x) + __popc(v1.y) + __popc(v1.z) + __popc(v1.w);
    for (int o = 16; o > 0; o >>= 1) s += __shfl_down_sync(0xffffffffu, s, o);
    int lane = threadIdx.x & 31, warp = threadIdx.x >> 5;
    if (lane == 0) wsum[warp] = s;
    __syncthreads();
    if (threadIdx.x == 0) {
        unsigned tt = 0;
#pragma unroll
        for (int w = 0; w < CTA / 32; w++) tt += wsum[w];
        g_chunk[blockIdx.x] = tt;
        __threadfence();
        unsigned d = atomicAdd(&g_done, 1u);
        is_last = (d == NCHUNK - 1);
    }
    __syncthreads();
    if (!is_last) return;

    // last block: exclusive scan of all 8192 counts (256 thr x 32 vals)
    __threadfence();
    int t = threadIdx.x;
    unsigned vals[32], ts = 0;
#pragma unroll
    for (int j = 0; j < 32; j++) { vals[j] = g_chunk[t * 32 + j]; ts += vals[j]; }
    // block exclusive scan of ts
    unsigned x = ts;
    for (int o = 1; o < 32; o <<= 1) {
        unsigned y = __shfl_up_sync(0xffffffffu, x, o);
        if (lane >= o) x += y;
    }
    if (lane == 31) wsum[warp] = x;
    __syncthreads();
    if (warp == 0) {
        unsigned y = (lane < CTA / 32) ? wsum[lane] : 0u;
        unsigned orig = y;
        for (int o = 1; o < 32; o <<= 1) {
            unsigned z = __shfl_up_sync(0xffffffffu, y, o);
            if (lane >= o) y += z;
        }
        if (lane < CTA / 32) wsum[lane] = y - orig;
    }
    __syncthreads();
    unsigned run = wsum[warp] + (x - ts);
#pragma unroll
    for (int j = 0; j < 32; j++) { g_chunk[t * 32 + j] = run; run += vals[j]; }
    if (t == CTA - 1) g_total = run;
    if (t == 0) g_done = 0u;   // self-reset for next graph replay
}

// ---- K3: emit — phase1 decode keys->smem, phase2 coalesced coord+feat out -
__global__ void __launch_bounds__(CTA)
k_emit(float4* __restrict__ out_coords, float* __restrict__ out_feats) {
    __shared__ unsigned wexc[32];
    __shared__ unsigned s_keys[EMIT_CAP];
    __shared__ unsigned s_base, s_agg;
    int t = threadIdx.x;
    unsigned base = blockIdx.x * WPB + t * WPT;
    unsigned words[WPT];
    const uint4* p = reinterpret_cast<const uint4*>(&g_bitmap[base]);
#pragma unroll
    for (int j = 0; j < WPT / 4; j++) {
        uint4 v = p[j];
        words[j * 4 + 0] = v.x; words[j * 4 + 1] = v.y;
        words[j * 4 + 2] = v.z; words[j * 4 + 3] = v.w;
    }
    unsigned tsum = 0;
#pragma unroll
    for (int j = 0; j < WPT; j++) tsum += __popc(words[j]);

    // block exclusive scan of per-thread sums
    int lane = t & 31, warp = t >> 5;
    unsigned x = tsum;
    for (int o = 1; o < 32; o <<= 1) {
        unsigned y = __shfl_up_sync(0xffffffffu, x, o);
        if (lane >= o) x += y;
    }
    if (lane == 31) wexc[warp] = x;
    __syncthreads();
    if (warp == 0) {   // all 32 lanes participate (shfl safety)
        unsigned y = (lane < CTA / 32) ? wexc[lane] : 0u;
        unsigned orig = y;
        for (int o = 1; o < 32; o <<= 1) {
            unsigned z = __shfl_up_sync(0xffffffffu, y, o);
            if (lane >= o) y += z;
        }
        if (lane < CTA / 32) wexc[lane] = y - orig;
    }
    __syncthreads();

    if (t == 0) s_base = g_chunk[blockIdx.x];
    if (t == CTA - 1) s_agg = wexc[warp] + x;   // block total unique
    __syncthreads();

    unsigned gbase = s_base;
    unsigned aggv = s_agg;
    unsigned lrun = wexc[warp] + (x - tsum);    // block-local rank

    // prefix at 4-word granularity: 2 entries per thread (WPT==8)
    unsigned c03 = __popc(words[0]) + __popc(words[1]) + __popc(words[2]) + __popc(words[3]);
    g_prefix4[(base >> 2) + 0] = gbase + lrun;
    g_prefix4[(base >> 2) + 1] = gbase + lrun + c03;

    // phase 1: decode set bits (64-bit pairs) into smem at local rank
#pragma unroll
    for (int j2 = 0; j2 < WPT / 2; j2++) {
        unsigned long long m = (unsigned long long)words[2 * j2] |
                               ((unsigned long long)words[2 * j2 + 1] << 32);
        unsigned kbase = (base + 2 * j2) << 5;
        while (m) {
            unsigned b = (unsigned)__ffsll((long long)m) - 1u;
            m &= m - 1ull;
            unsigned key = kbase + b;
            if (lrun < EMIT_CAP) {
                s_keys[lrun] = key;
            } else {            // overflow spill (statistically never taken)
                __stwt(&out_coords[gbase + lrun], make_float4(
                    (float)(key >> 21), (float)((key >> 14) & 127u),
                    (float)((key >> 7) & 127u), (float)(key & 127u)));
                __stwt(&out_feats[gbase + lrun], 0.0f);
            }
            lrun++;
        }
    }
    __syncthreads();

    // phase 2: coalesced write of coords + zero feats
    unsigned tot = aggv < EMIT_CAP ? aggv : EMIT_CAP;
    for (unsigned i = t; i < tot; i += CTA) {
        unsigned key = s_keys[i];
        __stwt(&out_coords[gbase + i], make_float4(
            (float)(key >> 21), (float)((key >> 14) & 127u),
            (float)((key >> 7) & 127u), (float)(key & 127u)));
        __stwt(&out_feats[gbase + i], 0.0f);
    }
}

// ---- K4: per-input rank lookup + atomicAdd feats, 2 points/thread ---------
__global__ void k_feats(const float* __restrict__ kern,
                        float* __restrict__ out_feats, int n) {
    int T = gridDim.x * blockDim.x;
    int i0 = blockIdx.x * blockDim.x + threadIdx.x;
    int i1 = i0 + T;
    bool v1 = i1 < n;
    if (i0 >= n) return;

    unsigned kp0 = __ldcs(&g_kp[i0]);
    unsigned kp1 = v1 ? __ldcs(&g_kp[i1]) : 0u;

    unsigned key0 = kp0 >> 3, pos0 = kp0 & 7u;
    unsigned key1 = kp1 >> 3, pos1 = kp1 & 7u;
    unsigned w0 = key0 >> 5, g0 = w0 >> 2;
    unsigned w1 = key1 >> 5, g1 = w1 >> 2;

    // front-batch gathers: one 16B bitmap quad + one prefix word per point
    const uint4* bm = reinterpret_cast<const uint4*>(g_bitmap);
    uint4 a = __ldg(&bm[g0]);
    uint4 b = v1 ? __ldg(&bm[g1]) : make_uint4(0, 0, 0, 0);
    unsigned r0 = __ldg(&g_prefix4[g0]);
    unsigned r1 = v1 ? __ldg(&g_prefix4[g1]) : 0u;

    {
        unsigned sub = w0 & 3u, bit = key0 & 31u;
        unsigned ws[4] = {a.x, a.y, a.z, a.w};
#pragma unroll
        for (unsigned j = 0; j < 4; j++)
            if (j < sub) r0 += __popc(ws[j]);
        r0 += __popc(ws[sub] & ((1u << bit) - 1u));
        atomicAdd(&out_feats[r0], (float)(1u << pos0) * __ldg(&kern[pos0]));
    }
    if (v1) {
        unsigned sub = w1 & 3u, bit = key1 & 31u;
        unsigned ws[4] = {b.x, b.y, b.z, b.w};
#pragma unroll
        for (unsigned j = 0; j < 4; j++)
            if (j < sub) r1 += __popc(ws[j]);
        r1 += __popc(ws[sub] & ((1u << bit) - 1u));
        atomicAdd(&out_feats[r1], (float)(1u << pos1) * __ldg(&kern[pos1]));
    }
}

// ---- K5: merged tail-fill + bitmap reset ----------------------------------
__global__ void k_finish(float4* __restrict__ out_coords, float* __restrict__ out_feats, int n) {
    unsigned gid = blockIdx.x * blockDim.x + threadIdx.x;
    unsigned stride = gridDim.x * blockDim.x;
    float4 neg = make_float4(-1.f, -1.f, -1.f, -1.f);
    unsigned total = g_total;
    for (unsigned i = total + gid; i < (unsigned)n; i += stride) {
        __stwt(&out_coords[i], neg);
        __stwt(&out_feats[i], 0.0f);
    }
    uint4 z = make_uint4(0u, 0u, 0u, 0u);
    uint4* p = reinterpret_cast<uint4*>(g_bitmap);
    unsigned n4 = NWORDS / 4;
    for (unsigned i = gid; i < n4; i += stride)
        p[i] = z;
}

extern "C" void kernel_launch(void* const* d_in, const int* in_sizes, int n_in,
                              void* d_out, int out_size) {
    const int4*  coords = (const int4*)d_in[0];
    const float* kern   = (const float*)d_in[1];
    int n = in_sizes[0] / 4;                // 4,000,000

    float*  out   = (float*)d_out;
    float4* out_c = (float4*)out;           // [n,4] coords as floats
    float*  out_f = out + (size_t)4 * n;    // [n] feats

    int gin2 = (n / 2 + 255) / 256;         // 2 points per thread (feats)
    int gin4 = (n / 4 + 255) / 256;         // 4 points per thread (scatter)

    k_scatter<<<gin4, 256>>>(coords, n);
    k_reduce <<<NCHUNK, CTA>>>();           // includes fused scan
    k_emit   <<<NCHUNK, CTA>>>(out_c, out_f);
    k_feats  <<<gin2, 256>>>(kern, out_f, n);   // slot 4: profiled
    k_finish <<<2048, 256>>>(out_c, out_f, n);
}